// round 14
// baseline (speedup 1.0000x reference)
#include <cuda_runtime.h>
#include <cuda_fp16.h>
#include <cstdint>

#define MAX_ENT   50000
#define MAX_E     1600000
#define MAX_REL   10       // N_REL - 1
#define C_DIM     128
#define C_VEC     (C_DIM / 4)    // 32 float4 per fp32 row
#define C_H2V     (C_DIM / 4)    // 32 uint2 (4 halves) per fp16 row
#define SCAN_TPB  1024

// ---------------- device scratch (static globals: no allocation allowed) ----
__device__ int            g_is64;
__device__ int            g_head[MAX_E];
__device__ unsigned short g_rank[MAX_E];     // within-head slot from histogram
__device__ unsigned       g_val[MAX_E];      // packed tail | (rel<<20)
__device__ unsigned       g_csr[MAX_E];      // CSR values: packed tail|rel
__device__ int            g_cnt[MAX_ENT];
__device__ int            g_row_start[MAX_ENT + 1];
__device__ int            g_part[64];        // per-block partial sums for scan
__device__ uint2          g_embH[MAX_ENT * C_H2V];  // fp16 input embeddings
__device__ uint2          g_embA[MAX_ENT * C_H2V];  // fp16 hop-1 output
__device__ uint2          g_embB[MAX_ENT * C_H2V];  // fp16 hop-2 output

// ---------------------------------------------------------------------------
// 0) fused: zero per-head counters + fp32->fp16 embedding convert + width
//    detection.  (int64 ids < 2^31 have all odd 32-bit words zero; effectively
//    impossible for the int32 interpretation of random ids in [0,50000).)
__global__ void init_convert_kernel(const unsigned* __restrict__ words,
                                    const float4* __restrict__ emb,
                                    int n_ent, int n_vec) {
    int i = blockIdx.x * blockDim.x + threadIdx.x;
    if (i < n_ent) g_cnt[i] = 0;
    if (i < n_vec) {
        float4 f = emb[i];
        __half2 a = __floats2half2_rn(f.x, f.y);
        __half2 b = __floats2half2_rn(f.z, f.w);
        uint2 q;
        q.x = *(unsigned*)&a;
        q.y = *(unsigned*)&b;
        g_embH[i] = q;
    }
    if (i == 0) {
        int is64 = 1;
        #pragma unroll 1
        for (int k = 1; k < 64; k += 2) {     // 32 odd-word checks suffice
            if (words[k] != 0u) { is64 = 0; break; }
        }
        g_is64 = is64;
    }
}

// 1) decode edges, histogram head degrees, record within-head rank
__global__ void build_a_kernel(const void* __restrict__ edge_index,
                               const void* __restrict__ edge_type, int E) {
    int j = blockIdx.x * blockDim.x + threadIdx.x;
    if (j >= E) return;
    int head, tail, rel;
    if (g_is64) {
        const long long* ei = (const long long*)edge_index;
        const long long* et = (const long long*)edge_type;
        head = (int)ei[j];
        tail = (int)ei[E + j];
        rel  = (int)et[j] - 1;
    } else {
        const int* ei = (const int*)edge_index;
        const int* et = (const int*)edge_type;
        head = ei[j];
        tail = ei[E + j];
        rel  = et[j] - 1;
    }
    g_head[j] = head;
    g_val[j]  = (unsigned)tail | ((unsigned)rel << 20);
    int r = atomicAdd(&g_cnt[head], 1);
    g_rank[j] = (unsigned short)r;           // degrees ~Poisson(32) << 65536
}

// 2) three-phase multi-block exclusive scan of g_cnt -> g_row_start
__global__ void scan1_kernel(int n_ent) {
    __shared__ int s[SCAN_TPB];
    int i = blockIdx.x * SCAN_TPB + threadIdx.x;
    s[threadIdx.x] = (i < n_ent) ? g_cnt[i] : 0;
    __syncthreads();
    for (int off = SCAN_TPB / 2; off > 0; off >>= 1) {
        if (threadIdx.x < off) s[threadIdx.x] += s[threadIdx.x + off];
        __syncthreads();
    }
    if (threadIdx.x == 0) g_part[blockIdx.x] = s[0];
}

__global__ void scan2_kernel(int nblocks, int n_ent) {
    if (threadIdx.x == 0 && blockIdx.x == 0) {
        int run = 0;
        for (int b = 0; b < nblocks; b++) {
            int c = g_part[b];
            g_part[b] = run;
            run += c;
        }
        g_row_start[n_ent] = run;
    }
}

__global__ void scan3_kernel(int n_ent) {
    __shared__ int s[SCAN_TPB];
    int i = blockIdx.x * SCAN_TPB + threadIdx.x;
    int x = (i < n_ent) ? g_cnt[i] : 0;
    s[threadIdx.x] = x;
    __syncthreads();
    // Hillis-Steele inclusive scan
    for (int off = 1; off < SCAN_TPB; off <<= 1) {
        int v = (threadIdx.x >= off) ? s[threadIdx.x - off] : 0;
        __syncthreads();
        s[threadIdx.x] += v;
        __syncthreads();
    }
    if (i < n_ent)
        g_row_start[i] = g_part[blockIdx.x] + s[threadIdx.x] - x;  // exclusive
}

// 3) fill CSR values -- atomic-free: pos = row_start[head] + rank
__global__ void build_b_kernel(int E) {
    int j = blockIdx.x * blockDim.x + threadIdx.x;
    if (j >= E) return;
    int pos = g_row_start[g_head[j]] + (int)g_rank[j];
    g_csr[pos] = g_val[j];
}

// ------------------------- hop helpers -------------------------------------
__device__ __forceinline__ void load_batch8(const uint2* __restrict__ src,
                                            int lane, int k,
                                            unsigned* v, uint2* p) {
    #pragma unroll
    for (int u = 0; u < 8; u++) v[u] = g_csr[k + u];
    #pragma unroll
    for (int u = 0; u < 8; u++)
        p[u] = src[(v[u] & 0xFFFFFu) * C_H2V + lane];
}

__device__ __forceinline__ void compute_batch8(const uint2* __restrict__ swh,
                                               int lane,
                                               const unsigned* v, const uint2* p,
                                               __half2& aA01, __half2& aA23,
                                               __half2& aB01, __half2& aB23) {
    #pragma unroll
    for (int u = 0; u < 8; u++) {
        uint2 w = swh[(v[u] >> 20) * C_VEC + lane];
        __half2 x01 = *(__half2*)&p[u].x;
        __half2 x23 = *(__half2*)&p[u].y;
        __half2 w01 = *(__half2*)&w.x;
        __half2 w23 = *(__half2*)&w.y;
        if (u & 1) {
            aB01 = __hfma2(x01, w01, aB01);
            aB23 = __hfma2(x23, w23, aB23);
        } else {
            aA01 = __hfma2(x01, w01, aA01);
            aA23 = __hfma2(x23, w23, aA23);
        }
    }
}

// 4) fused hop.  Double-buffered 8-wide software pipeline — next batch's
//    csr+gather loads issue before current batch's HFMA2s, breaking the WAR
//    serialization at batch boundaries.
//    hop 0: src embH -> dst embA.   hop 1: embA -> embB.
//    hop 2: embB -> res = emb32 + h1 + h2 + h3  (fused finish).
__global__ __launch_bounds__(256, 2)
void hop_kernel(const float4* __restrict__ weight,
                const float4* __restrict__ emb32,
                float4* __restrict__ res,
                int n_ent, int n_rel, int hop) {
    __shared__ uint2 swh[MAX_REL * C_VEC];   // 2.5 KB: fp16 relation rows
    for (int i = threadIdx.x; i < n_rel * C_VEC; i += blockDim.x) {
        float4 w = weight[i];
        __half2 a = __floats2half2_rn(w.x, w.y);
        __half2 b = __floats2half2_rn(w.z, w.w);
        uint2 q;
        q.x = *(unsigned*)&a;
        q.y = *(unsigned*)&b;
        swh[i] = q;
    }
    __syncthreads();

    const uint2* src = (hop == 0) ? (const uint2*)g_embH
                     : (hop == 1) ? (const uint2*)g_embA
                                  : (const uint2*)g_embB;

    int warp = (blockIdx.x * blockDim.x + threadIdx.x) >> 5;
    int lane = threadIdx.x & 31;
    if (warp >= n_ent) return;

    const int start = g_row_start[warp];
    const int end   = g_row_start[warp + 1];

    const __half2 hz = __float2half2_rn(0.f);
    __half2 aA01 = hz, aA23 = hz;   // even-parity accumulators
    __half2 aB01 = hz, aB23 = hz;   // odd-parity accumulators

    unsigned vA[8], vB[8];
    uint2    pA[8], pB[8];

    int k = start;
    bool valid = (k + 7 < end);
    if (valid) load_batch8(src, lane, k, vA, pA);
    while (valid) {
        int kn = k + 8;
        bool nvalid = (kn + 7 < end);
        if (nvalid) load_batch8(src, lane, kn, vB, pB);     // prefetch B
        compute_batch8(swh, lane, vA, pA, aA01, aA23, aB01, aB23);
        k = kn;
        if (!nvalid) break;

        kn = k + 8;
        nvalid = (kn + 7 < end);
        if (nvalid) load_batch8(src, lane, kn, vA, pA);     // prefetch A
        compute_batch8(swh, lane, vB, pB, aA01, aA23, aB01, aB23);
        k = kn;
        valid = nvalid;
    }
    // scalar tail (< 8 edges)
    for (; k < end; k++) {
        unsigned v = g_csr[k];
        uint2 p = src[(v & 0xFFFFFu) * C_H2V + lane];
        uint2 w = swh[(v >> 20) * C_VEC + lane];
        __half2 x01 = *(__half2*)&p.x;
        __half2 x23 = *(__half2*)&p.y;
        __half2 w01 = *(__half2*)&w.x;
        __half2 w23 = *(__half2*)&w.y;
        if (k & 1) {
            aB01 = __hfma2(x01, w01, aB01);
            aB23 = __hfma2(x23, w23, aB23);
        } else {
            aA01 = __hfma2(x01, w01, aA01);
            aA23 = __hfma2(x23, w23, aA23);
        }
    }

    // fp32 combine of the two half2 partial sums
    float2 fA01 = __half22float2(aA01), fB01 = __half22float2(aB01);
    float2 fA23 = __half22float2(aA23), fB23 = __half22float2(aB23);
    float4 acc = make_float4(fA01.x + fB01.x, fA01.y + fB01.y,
                             fA23.x + fB23.x, fA23.y + fB23.y);

    // scatter_mean
    float inv = 1.0f / fmaxf((float)(end - start), 1.0f);
    acc.x *= inv; acc.y *= inv; acc.z *= inv; acc.w *= inv;

    // L2 norm across 128 channels
    float ss = acc.x * acc.x + acc.y * acc.y + acc.z * acc.z + acc.w * acc.w;
    #pragma unroll
    for (int off = 16; off > 0; off >>= 1)
        ss += __shfl_xor_sync(0xFFFFFFFFu, ss, off);
    float scale = 1.0f / fmaxf(sqrtf(ss), 1e-12f);

    float4 o = make_float4(acc.x * scale, acc.y * scale,
                           acc.z * scale, acc.w * scale);

    int idx = warp * C_H2V + lane;

    if (hop < 2) {
        uint2* dst = (hop == 0) ? (uint2*)g_embA : (uint2*)g_embB;
        __half2 ha = __floats2half2_rn(o.x, o.y);
        __half2 hb = __floats2half2_rn(o.z, o.w);
        uint2 q;
        q.x = *(unsigned*)&ha;
        q.y = *(unsigned*)&hb;
        dst[idx] = q;
    } else {
        // fused finish: res = entity_emb + h1 + h2 + h3
        float4 r = emb32[idx];
        uint2 a = g_embA[idx];
        uint2 b = g_embB[idx];
        float2 ax = __half22float2(*(__half2*)&a.x);
        float2 ay = __half22float2(*(__half2*)&a.y);
        float2 bx = __half22float2(*(__half2*)&b.x);
        float2 by = __half22float2(*(__half2*)&b.y);
        r.x += ax.x + bx.x + o.x;
        r.y += ax.y + bx.y + o.y;
        r.z += ay.x + by.x + o.z;
        r.w += ay.y + by.y + o.w;
        res[idx] = r;
    }
}

// ---------------------------------------------------------------------------
extern "C" void kernel_launch(void* const* d_in, const int* in_sizes, int n_in,
                              void* d_out, int out_size) {
    const float*  entity_emb = (const float*)d_in[0];
    const void*   edge_index = d_in[1];
    const void*   edge_type  = d_in[2];
    const float*  weight     = (const float*)d_in[3];

    const int n_ent = in_sizes[0] / C_DIM;     // 50000
    const int E     = in_sizes[2];             // 1600000
    const int n_rel = in_sizes[3] / C_DIM;     // 10

    const int TB = 256;
    const int n_vec = n_ent * C_VEC;
    const int scan_blocks = (n_ent + SCAN_TPB - 1) / SCAN_TPB;

    // CSR build + fp16 convert (once per launch; reused across the 3 hops)
    init_convert_kernel<<<(n_vec + TB - 1) / TB, TB>>>(
        (const unsigned*)edge_index, (const float4*)entity_emb, n_ent, n_vec);
    build_a_kernel<<<(E + TB - 1) / TB, TB>>>(edge_index, edge_type, E);
    scan1_kernel<<<scan_blocks, SCAN_TPB>>>(n_ent);
    scan2_kernel<<<1, 32>>>(scan_blocks, n_ent);
    scan3_kernel<<<scan_blocks, SCAN_TPB>>>(n_ent);
    build_b_kernel<<<(E + TB - 1) / TB, TB>>>(E);

    // 3 fused hops, one warp per entity (8 warps/block); hop 2 also writes res
    const int hop_blocks = (n_ent * 32 + TB - 1) / TB;
    hop_kernel<<<hop_blocks, TB>>>((const float4*)weight,
                                   (const float4*)entity_emb,
                                   (float4*)d_out, n_ent, n_rel, 0);
    hop_kernel<<<hop_blocks, TB>>>((const float4*)weight,
                                   (const float4*)entity_emb,
                                   (float4*)d_out, n_ent, n_rel, 1);
    hop_kernel<<<hop_blocks, TB>>>((const float4*)weight,
                                   (const float4*)entity_emb,
                                   (float4*)d_out, n_ent, n_rel, 2);
}

// round 15
// speedup vs baseline: 1.5457x; 1.5457x over previous
#include <cuda_runtime.h>
#include <cuda_fp16.h>
#include <cstdint>

#define MAX_ENT   50000
#define MAX_E     1600000
#define MAX_REL   10       // N_REL - 1
#define C_DIM     128
#define C_VEC     (C_DIM / 4)    // 32 float4 per fp32 row
#define C_H2V     (C_DIM / 4)    // 32 uint2 (4 halves) per fp16 row
#define SCAN_TPB  1024

// ---------------- device scratch (static globals: no allocation allowed) ----
__device__ int            g_is64;
__device__ int            g_head[MAX_E];
__device__ unsigned short g_rank[MAX_E];     // within-head slot from histogram
__device__ unsigned       g_val[MAX_E];      // packed tail | (rel<<20)
__device__ unsigned       g_csr[MAX_E];      // CSR values: packed tail|rel
__device__ int            g_cnt[MAX_ENT];
__device__ int            g_row_start[MAX_ENT + 1];
__device__ int            g_part[64];        // per-block partial sums for scan
__device__ uint2          g_embH[MAX_ENT * C_H2V];  // fp16 input embeddings
__device__ uint2          g_embA[MAX_ENT * C_H2V];  // fp16 hop-1 output
__device__ uint2          g_embB[MAX_ENT * C_H2V];  // fp16 hop-2 output

// ---------------------------------------------------------------------------
// 0) fused: zero per-head counters + fp32->fp16 embedding convert + width
//    detection.  (int64 ids < 2^31 have all odd 32-bit words zero; effectively
//    impossible for the int32 interpretation of random ids in [0,50000).)
__global__ void init_convert_kernel(const unsigned* __restrict__ words,
                                    const float4* __restrict__ emb,
                                    int n_ent, int n_vec) {
    int i = blockIdx.x * blockDim.x + threadIdx.x;
    if (i < n_ent) g_cnt[i] = 0;
    if (i < n_vec) {
        float4 f = emb[i];
        __half2 a = __floats2half2_rn(f.x, f.y);
        __half2 b = __floats2half2_rn(f.z, f.w);
        uint2 q;
        q.x = *(unsigned*)&a;
        q.y = *(unsigned*)&b;
        g_embH[i] = q;
    }
    if (i == 0) {
        int is64 = 1;
        #pragma unroll 1
        for (int k = 1; k < 64; k += 2) {     // 32 odd-word checks suffice
            if (words[k] != 0u) { is64 = 0; break; }
        }
        g_is64 = is64;
    }
}

// 1) decode edges, histogram head degrees, record within-head rank
__global__ void build_a_kernel(const void* __restrict__ edge_index,
                               const void* __restrict__ edge_type, int E) {
    int j = blockIdx.x * blockDim.x + threadIdx.x;
    if (j >= E) return;
    int head, tail, rel;
    if (g_is64) {
        const long long* ei = (const long long*)edge_index;
        const long long* et = (const long long*)edge_type;
        head = (int)ei[j];
        tail = (int)ei[E + j];
        rel  = (int)et[j] - 1;
    } else {
        const int* ei = (const int*)edge_index;
        const int* et = (const int*)edge_type;
        head = ei[j];
        tail = ei[E + j];
        rel  = et[j] - 1;
    }
    g_head[j] = head;
    g_val[j]  = (unsigned)tail | ((unsigned)rel << 20);
    int r = atomicAdd(&g_cnt[head], 1);
    g_rank[j] = (unsigned short)r;           // degrees ~Poisson(32) << 65536
}

// 2) three-phase multi-block exclusive scan of g_cnt -> g_row_start
__global__ void scan1_kernel(int n_ent) {
    __shared__ int s[SCAN_TPB];
    int i = blockIdx.x * SCAN_TPB + threadIdx.x;
    s[threadIdx.x] = (i < n_ent) ? g_cnt[i] : 0;
    __syncthreads();
    for (int off = SCAN_TPB / 2; off > 0; off >>= 1) {
        if (threadIdx.x < off) s[threadIdx.x] += s[threadIdx.x + off];
        __syncthreads();
    }
    if (threadIdx.x == 0) g_part[blockIdx.x] = s[0];
}

// parallel exclusive scan of <=64 block partials (64 threads, 1 block)
__global__ void scan2_kernel(int nblocks, int n_ent) {
    __shared__ int s[64];
    int t = threadIdx.x;
    int x = (t < nblocks) ? g_part[t] : 0;
    s[t] = x;
    __syncthreads();
    #pragma unroll
    for (int off = 1; off < 64; off <<= 1) {
        int v = (t >= off) ? s[t - off] : 0;
        __syncthreads();
        s[t] += v;
        __syncthreads();
    }
    if (t < nblocks) g_part[t] = s[t] - x;          // exclusive
    if (t == 63)     g_row_start[n_ent] = s[63];    // total edge count
}

__global__ void scan3_kernel(int n_ent) {
    __shared__ int s[SCAN_TPB];
    int i = blockIdx.x * SCAN_TPB + threadIdx.x;
    int x = (i < n_ent) ? g_cnt[i] : 0;
    s[threadIdx.x] = x;
    __syncthreads();
    // Hillis-Steele inclusive scan
    for (int off = 1; off < SCAN_TPB; off <<= 1) {
        int v = (threadIdx.x >= off) ? s[threadIdx.x - off] : 0;
        __syncthreads();
        s[threadIdx.x] += v;
        __syncthreads();
    }
    if (i < n_ent)
        g_row_start[i] = g_part[blockIdx.x] + s[threadIdx.x] - x;  // exclusive
}

// 3) fill CSR values -- atomic-free: pos = row_start[head] + rank
__global__ void build_b_kernel(int E) {
    int j = blockIdx.x * blockDim.x + threadIdx.x;
    if (j >= E) return;
    int pos = g_row_start[g_head[j]] + (int)g_rank[j];
    g_csr[pos] = g_val[j];
}

// 4) fused hop — R12-proven body: flat 16-wide unroll (16 outstanding uint2
//    gathers per lane), HFMA2 parity-split accumulators, fp32 combine.
//    hop 0: src embH -> dst embA.   hop 1: embA -> embB.
//    hop 2: embB -> res = emb32 + h1 + h2 + h3  (fused finish).
__global__ __launch_bounds__(256)
void hop_kernel(const float4* __restrict__ weight,
                const float4* __restrict__ emb32,
                float4* __restrict__ res,
                int n_ent, int n_rel, int hop) {
    __shared__ uint2 swh[MAX_REL * C_VEC];   // 2.5 KB: fp16 relation rows
    for (int i = threadIdx.x; i < n_rel * C_VEC; i += blockDim.x) {
        float4 w = weight[i];
        __half2 a = __floats2half2_rn(w.x, w.y);
        __half2 b = __floats2half2_rn(w.z, w.w);
        uint2 q;
        q.x = *(unsigned*)&a;
        q.y = *(unsigned*)&b;
        swh[i] = q;
    }
    __syncthreads();

    const uint2* src = (hop == 0) ? (const uint2*)g_embH
                     : (hop == 1) ? (const uint2*)g_embA
                                  : (const uint2*)g_embB;

    int warp = (blockIdx.x * blockDim.x + threadIdx.x) >> 5;
    int lane = threadIdx.x & 31;
    if (warp >= n_ent) return;

    const int start = g_row_start[warp];
    const int end   = g_row_start[warp + 1];

    const __half2 hz = __float2half2_rn(0.f);
    __half2 aA01 = hz, aA23 = hz;   // even-parity accumulators
    __half2 aB01 = hz, aB23 = hz;   // odd-parity accumulators

    int k = start;
    // 16-wide unroll: 16 independent 64-bit gathers in flight per lane
    for (; k + 15 < end; k += 16) {
        unsigned v[16];
        uint2 p[16];
        #pragma unroll
        for (int u = 0; u < 16; u++) v[u] = g_csr[k + u];
        #pragma unroll
        for (int u = 0; u < 16; u++)
            p[u] = src[(v[u] & 0xFFFFFu) * C_H2V + lane];
        #pragma unroll
        for (int u = 0; u < 16; u++) {
            uint2 w = swh[(v[u] >> 20) * C_VEC + lane];
            __half2 x01 = *(__half2*)&p[u].x;
            __half2 x23 = *(__half2*)&p[u].y;
            __half2 w01 = *(__half2*)&w.x;
            __half2 w23 = *(__half2*)&w.y;
            if (u & 1) {
                aB01 = __hfma2(x01, w01, aB01);
                aB23 = __hfma2(x23, w23, aB23);
            } else {
                aA01 = __hfma2(x01, w01, aA01);
                aA23 = __hfma2(x23, w23, aA23);
            }
        }
    }
    // 8-wide cleanup
    for (; k + 7 < end; k += 8) {
        unsigned v[8];
        uint2 p[8];
        #pragma unroll
        for (int u = 0; u < 8; u++) v[u] = g_csr[k + u];
        #pragma unroll
        for (int u = 0; u < 8; u++)
            p[u] = src[(v[u] & 0xFFFFFu) * C_H2V + lane];
        #pragma unroll
        for (int u = 0; u < 8; u++) {
            uint2 w = swh[(v[u] >> 20) * C_VEC + lane];
            __half2 x01 = *(__half2*)&p[u].x;
            __half2 x23 = *(__half2*)&p[u].y;
            __half2 w01 = *(__half2*)&w.x;
            __half2 w23 = *(__half2*)&w.y;
            if (u & 1) {
                aB01 = __hfma2(x01, w01, aB01);
                aB23 = __hfma2(x23, w23, aB23);
            } else {
                aA01 = __hfma2(x01, w01, aA01);
                aA23 = __hfma2(x23, w23, aA23);
            }
        }
    }
    for (; k < end; k++) {
        unsigned v = g_csr[k];
        uint2 p = src[(v & 0xFFFFFu) * C_H2V + lane];
        uint2 w = swh[(v >> 20) * C_VEC + lane];
        __half2 x01 = *(__half2*)&p.x;
        __half2 x23 = *(__half2*)&p.y;
        __half2 w01 = *(__half2*)&w.x;
        __half2 w23 = *(__half2*)&w.y;
        if (k & 1) {
            aB01 = __hfma2(x01, w01, aB01);
            aB23 = __hfma2(x23, w23, aB23);
        } else {
            aA01 = __hfma2(x01, w01, aA01);
            aA23 = __hfma2(x23, w23, aA23);
        }
    }

    // fp32 combine of the two half2 partial sums
    float2 fA01 = __half22float2(aA01), fB01 = __half22float2(aB01);
    float2 fA23 = __half22float2(aA23), fB23 = __half22float2(aB23);
    float4 acc = make_float4(fA01.x + fB01.x, fA01.y + fB01.y,
                             fA23.x + fB23.x, fA23.y + fB23.y);

    // scatter_mean
    float inv = 1.0f / fmaxf((float)(end - start), 1.0f);
    acc.x *= inv; acc.y *= inv; acc.z *= inv; acc.w *= inv;

    // L2 norm across 128 channels
    float ss = acc.x * acc.x + acc.y * acc.y + acc.z * acc.z + acc.w * acc.w;
    #pragma unroll
    for (int off = 16; off > 0; off >>= 1)
        ss += __shfl_xor_sync(0xFFFFFFFFu, ss, off);
    float scale = 1.0f / fmaxf(sqrtf(ss), 1e-12f);

    float4 o = make_float4(acc.x * scale, acc.y * scale,
                           acc.z * scale, acc.w * scale);

    int idx = warp * C_H2V + lane;

    if (hop < 2) {
        uint2* dst = (hop == 0) ? (uint2*)g_embA : (uint2*)g_embB;
        __half2 ha = __floats2half2_rn(o.x, o.y);
        __half2 hb = __floats2half2_rn(o.z, o.w);
        uint2 q;
        q.x = *(unsigned*)&ha;
        q.y = *(unsigned*)&hb;
        dst[idx] = q;
    } else {
        // fused finish: res = entity_emb + h1 + h2 + h3
        float4 r = emb32[idx];
        uint2 a = g_embA[idx];
        uint2 b = g_embB[idx];
        float2 ax = __half22float2(*(__half2*)&a.x);
        float2 ay = __half22float2(*(__half2*)&a.y);
        float2 bx = __half22float2(*(__half2*)&b.x);
        float2 by = __half22float2(*(__half2*)&b.y);
        r.x += ax.x + bx.x + o.x;
        r.y += ax.y + bx.y + o.y;
        r.z += ay.x + by.x + o.z;
        r.w += ay.y + by.y + o.w;
        res[idx] = r;
    }
}

// ---------------------------------------------------------------------------
extern "C" void kernel_launch(void* const* d_in, const int* in_sizes, int n_in,
                              void* d_out, int out_size) {
    const float*  entity_emb = (const float*)d_in[0];
    const void*   edge_index = d_in[1];
    const void*   edge_type  = d_in[2];
    const float*  weight     = (const float*)d_in[3];

    const int n_ent = in_sizes[0] / C_DIM;     // 50000
    const int E     = in_sizes[2];             // 1600000
    const int n_rel = in_sizes[3] / C_DIM;     // 10

    const int TB = 256;
    const int n_vec = n_ent * C_VEC;
    const int scan_blocks = (n_ent + SCAN_TPB - 1) / SCAN_TPB;

    // CSR build + fp16 convert (once per launch; reused across the 3 hops)
    init_convert_kernel<<<(n_vec + TB - 1) / TB, TB>>>(
        (const unsigned*)edge_index, (const float4*)entity_emb, n_ent, n_vec);
    build_a_kernel<<<(E + TB - 1) / TB, TB>>>(edge_index, edge_type, E);
    scan1_kernel<<<scan_blocks, SCAN_TPB>>>(n_ent);
    scan2_kernel<<<1, 64>>>(scan_blocks, n_ent);
    scan3_kernel<<<scan_blocks, SCAN_TPB>>>(n_ent);
    build_b_kernel<<<(E + TB - 1) / TB, TB>>>(E);

    // 3 fused hops, one warp per entity (8 warps/block); hop 2 also writes res
    const int hop_blocks = (n_ent * 32 + TB - 1) / TB;
    hop_kernel<<<hop_blocks, TB>>>((const float4*)weight,
                                   (const float4*)entity_emb,
                                   (float4*)d_out, n_ent, n_rel, 0);
    hop_kernel<<<hop_blocks, TB>>>((const float4*)weight,
                                   (const float4*)entity_emb,
                                   (float4*)d_out, n_ent, n_rel, 1);
    hop_kernel<<<hop_blocks, TB>>>((const float4*)weight,
                                   (const float4*)entity_emb,
                                   (float4*)d_out, n_ent, n_rel, 2);
}

// round 16
// speedup vs baseline: 1.5621x; 1.0106x over previous
#include <cuda_runtime.h>
#include <cuda_fp16.h>
#include <cstdint>

#define MAX_ENT   50000
#define MAX_E     1600000
#define MAX_REL   10       // N_REL - 1
#define C_DIM     128
#define C_VEC     (C_DIM / 4)    // 32 float4 per fp32 row
#define C_H2V     (C_DIM / 4)    // 32 uint2 (4 halves) per fp16 row
#define SCAN_TPB  1024

// ---------------- device scratch (static globals: no allocation allowed) ----
__device__ int            g_is64;
__device__ int            g_head[MAX_E];
__device__ unsigned short g_rank[MAX_E];     // within-head slot from histogram
__device__ unsigned       g_val[MAX_E];      // packed tail | (rel<<20)
__device__ unsigned       g_csr[MAX_E];      // CSR values: packed tail|rel
__device__ int            g_cnt[MAX_ENT];
__device__ int            g_row_start[MAX_ENT + 1];
__device__ int            g_part[64];        // per-block partial sums for scan
__device__ uint2          g_embH[MAX_ENT * C_H2V];  // fp16 input embeddings
__device__ uint2          g_embA[MAX_ENT * C_H2V];  // fp16 hop-1 output
__device__ uint2          g_embB[MAX_ENT * C_H2V];  // fp16 hop-2 output

// ---------------------------------------------------------------------------
// 0) fused: zero per-head counters + fp32->fp16 embedding convert + width
//    detection.  (int64 ids < 2^31 have all odd 32-bit words zero; effectively
//    impossible for the int32 interpretation of random ids in [0,50000).)
__global__ void init_convert_kernel(const unsigned* __restrict__ words,
                                    const float4* __restrict__ emb,
                                    int n_ent, int n_vec) {
    int i = blockIdx.x * blockDim.x + threadIdx.x;
    if (i < n_ent) g_cnt[i] = 0;
    if (i < n_vec) {
        float4 f = emb[i];
        __half2 a = __floats2half2_rn(f.x, f.y);
        __half2 b = __floats2half2_rn(f.z, f.w);
        uint2 q;
        q.x = *(unsigned*)&a;
        q.y = *(unsigned*)&b;
        g_embH[i] = q;
    }
    if (i == 0) {
        int is64 = 1;
        #pragma unroll 1
        for (int k = 1; k < 64; k += 2) {     // 32 odd-word checks suffice
            if (words[k] != 0u) { is64 = 0; break; }
        }
        g_is64 = is64;
    }
}

// 1) decode edges, histogram head degrees, record within-head rank
__global__ void build_a_kernel(const void* __restrict__ edge_index,
                               const void* __restrict__ edge_type, int E) {
    int j = blockIdx.x * blockDim.x + threadIdx.x;
    if (j >= E) return;
    int head, tail, rel;
    if (g_is64) {
        const long long* ei = (const long long*)edge_index;
        const long long* et = (const long long*)edge_type;
        head = (int)ei[j];
        tail = (int)ei[E + j];
        rel  = (int)et[j] - 1;
    } else {
        const int* ei = (const int*)edge_index;
        const int* et = (const int*)edge_type;
        head = ei[j];
        tail = ei[E + j];
        rel  = et[j] - 1;
    }
    g_head[j] = head;
    g_val[j]  = (unsigned)tail | ((unsigned)rel << 20);
    int r = atomicAdd(&g_cnt[head], 1);
    g_rank[j] = (unsigned short)r;           // degrees ~Poisson(32) << 65536
}

// 2a) per-block reduce of g_cnt -> g_part[block]
__global__ void scan1_kernel(int n_ent) {
    __shared__ int s[SCAN_TPB];
    int i = blockIdx.x * SCAN_TPB + threadIdx.x;
    s[threadIdx.x] = (i < n_ent) ? g_cnt[i] : 0;
    __syncthreads();
    for (int off = SCAN_TPB / 2; off > 0; off >>= 1) {
        if (threadIdx.x < off) s[threadIdx.x] += s[threadIdx.x + off];
        __syncthreads();
    }
    if (threadIdx.x == 0) g_part[blockIdx.x] = s[0];
}

// 2b) per-block scan + inline redundant scan of the <=64 partials (each
//     block derives its own offset; no separate middle kernel / launch gap)
__global__ void scan3_kernel(int nblocks, int n_ent) {
    __shared__ int s[SCAN_TPB];
    __shared__ int sp[64];

    // redundant exclusive scan of block partials (cheap: 64 elements)
    if (threadIdx.x < 64) {
        int x = (threadIdx.x < nblocks) ? g_part[threadIdx.x] : 0;
        sp[threadIdx.x] = x;
    }
    __syncthreads();
    if (threadIdx.x < 64) {
        // serial-in-shared is fine at this size; do Hillis-Steele with 64 lanes
        #pragma unroll
        for (int off = 1; off < 64; off <<= 1) {
            int v = (threadIdx.x >= off) ? sp[threadIdx.x - off] : 0;
            __syncwarp(0xFFFFFFFFu);
            // need full 64-thread sync; use barrier below instead
            sp[threadIdx.x] += v;
            __syncwarp(0xFFFFFFFFu);
        }
    }
    __syncthreads();
    // NOTE: the loop above is only safe within a warp; redo properly with
    // block-wide barriers (correctness first — 64 spans 2 warps):
    if (threadIdx.x == 0) {
        int run = 0;
        #pragma unroll 1
        for (int b = 0; b < 64; b++) {
            int c = (b < nblocks) ? g_part[b] : 0;
            sp[b] = run;           // exclusive prefix
            run += c;
        }
        sp[63 + 1 - 1] = sp[63];   // no-op keep
        if (blockIdx.x == gridDim.x - 1) g_row_start[n_ent] = run;
    }
    __syncthreads();

    int block_off = sp[blockIdx.x];

    int i = blockIdx.x * SCAN_TPB + threadIdx.x;
    int x = (i < n_ent) ? g_cnt[i] : 0;
    s[threadIdx.x] = x;
    __syncthreads();
    // Hillis-Steele inclusive scan over the block
    for (int off = 1; off < SCAN_TPB; off <<= 1) {
        int v = (threadIdx.x >= off) ? s[threadIdx.x - off] : 0;
        __syncthreads();
        s[threadIdx.x] += v;
        __syncthreads();
    }
    if (i < n_ent)
        g_row_start[i] = block_off + s[threadIdx.x] - x;  // exclusive
}

// 3) fill CSR values -- atomic-free: pos = row_start[head] + rank
__global__ void build_b_kernel(int E) {
    int j = blockIdx.x * blockDim.x + threadIdx.x;
    if (j >= E) return;
    int pos = g_row_start[g_head[j]] + (int)g_rank[j];
    g_csr[pos] = g_val[j];
}

// 4) fused hop — R12/R15-proven body: flat 16-wide unroll (16 outstanding
//    uint2 gathers per lane), HFMA2 parity-split accumulators, fp32 combine.
//    hop 0: src embH -> dst embA.   hop 1: embA -> embB.
//    hop 2: embB -> res = emb32 + h1 + h2 + h3  (fused finish).
__global__ __launch_bounds__(256)
void hop_kernel(const float4* __restrict__ weight,
                const float4* __restrict__ emb32,
                float4* __restrict__ res,
                int n_ent, int n_rel, int hop) {
    __shared__ uint2 swh[MAX_REL * C_VEC];   // 2.5 KB: fp16 relation rows
    for (int i = threadIdx.x; i < n_rel * C_VEC; i += blockDim.x) {
        float4 w = weight[i];
        __half2 a = __floats2half2_rn(w.x, w.y);
        __half2 b = __floats2half2_rn(w.z, w.w);
        uint2 q;
        q.x = *(unsigned*)&a;
        q.y = *(unsigned*)&b;
        swh[i] = q;
    }
    __syncthreads();

    const uint2* src = (hop == 0) ? (const uint2*)g_embH
                     : (hop == 1) ? (const uint2*)g_embA
                                  : (const uint2*)g_embB;

    int warp = (blockIdx.x * blockDim.x + threadIdx.x) >> 5;
    int lane = threadIdx.x & 31;
    if (warp >= n_ent) return;

    const int start = g_row_start[warp];
    const int end   = g_row_start[warp + 1];

    const __half2 hz = __float2half2_rn(0.f);
    __half2 aA01 = hz, aA23 = hz;   // even-parity accumulators
    __half2 aB01 = hz, aB23 = hz;   // odd-parity accumulators

    int k = start;
    // 16-wide unroll: 16 independent 64-bit gathers in flight per lane
    for (; k + 15 < end; k += 16) {
        unsigned v[16];
        uint2 p[16];
        #pragma unroll
        for (int u = 0; u < 16; u++) v[u] = g_csr[k + u];
        #pragma unroll
        for (int u = 0; u < 16; u++)
            p[u] = src[(v[u] & 0xFFFFFu) * C_H2V + lane];
        #pragma unroll
        for (int u = 0; u < 16; u++) {
            uint2 w = swh[(v[u] >> 20) * C_VEC + lane];
            __half2 x01 = *(__half2*)&p[u].x;
            __half2 x23 = *(__half2*)&p[u].y;
            __half2 w01 = *(__half2*)&w.x;
            __half2 w23 = *(__half2*)&w.y;
            if (u & 1) {
                aB01 = __hfma2(x01, w01, aB01);
                aB23 = __hfma2(x23, w23, aB23);
            } else {
                aA01 = __hfma2(x01, w01, aA01);
                aA23 = __hfma2(x23, w23, aA23);
            }
        }
    }
    // 8-wide cleanup
    for (; k + 7 < end; k += 8) {
        unsigned v[8];
        uint2 p[8];
        #pragma unroll
        for (int u = 0; u < 8; u++) v[u] = g_csr[k + u];
        #pragma unroll
        for (int u = 0; u < 8; u++)
            p[u] = src[(v[u] & 0xFFFFFu) * C_H2V + lane];
        #pragma unroll
        for (int u = 0; u < 8; u++) {
            uint2 w = swh[(v[u] >> 20) * C_VEC + lane];
            __half2 x01 = *(__half2*)&p[u].x;
            __half2 x23 = *(__half2*)&p[u].y;
            __half2 w01 = *(__half2*)&w.x;
            __half2 w23 = *(__half2*)&w.y;
            if (u & 1) {
                aB01 = __hfma2(x01, w01, aB01);
                aB23 = __hfma2(x23, w23, aB23);
            } else {
                aA01 = __hfma2(x01, w01, aA01);
                aA23 = __hfma2(x23, w23, aA23);
            }
        }
    }
    for (; k < end; k++) {
        unsigned v = g_csr[k];
        uint2 p = src[(v & 0xFFFFFu) * C_H2V + lane];
        uint2 w = swh[(v >> 20) * C_VEC + lane];
        __half2 x01 = *(__half2*)&p.x;
        __half2 x23 = *(__half2*)&p.y;
        __half2 w01 = *(__half2*)&w.x;
        __half2 w23 = *(__half2*)&w.y;
        if (k & 1) {
            aB01 = __hfma2(x01, w01, aB01);
            aB23 = __hfma2(x23, w23, aB23);
        } else {
            aA01 = __hfma2(x01, w01, aA01);
            aA23 = __hfma2(x23, w23, aA23);
        }
    }

    // fp32 combine of the two half2 partial sums
    float2 fA01 = __half22float2(aA01), fB01 = __half22float2(aB01);
    float2 fA23 = __half22float2(aA23), fB23 = __half22float2(aB23);
    float4 acc = make_float4(fA01.x + fB01.x, fA01.y + fB01.y,
                             fA23.x + fB23.x, fA23.y + fB23.y);

    // scatter_mean
    float inv = 1.0f / fmaxf((float)(end - start), 1.0f);
    acc.x *= inv; acc.y *= inv; acc.z *= inv; acc.w *= inv;

    // L2 norm across 128 channels
    float ss = acc.x * acc.x + acc.y * acc.y + acc.z * acc.z + acc.w * acc.w;
    #pragma unroll
    for (int off = 16; off > 0; off >>= 1)
        ss += __shfl_xor_sync(0xFFFFFFFFu, ss, off);
    float scale = 1.0f / fmaxf(sqrtf(ss), 1e-12f);

    float4 o = make_float4(acc.x * scale, acc.y * scale,
                           acc.z * scale, acc.w * scale);

    int idx = warp * C_H2V + lane;

    if (hop < 2) {
        uint2* dst = (hop == 0) ? (uint2*)g_embA : (uint2*)g_embB;
        __half2 ha = __floats2half2_rn(o.x, o.y);
        __half2 hb = __floats2half2_rn(o.z, o.w);
        uint2 q;
        q.x = *(unsigned*)&ha;
        q.y = *(unsigned*)&hb;
        dst[idx] = q;
    } else {
        // fused finish: res = entity_emb + h1 + h2 + h3
        float4 r = emb32[idx];
        uint2 a = g_embA[idx];
        uint2 b = g_embB[idx];
        float2 ax = __half22float2(*(__half2*)&a.x);
        float2 ay = __half22float2(*(__half2*)&a.y);
        float2 bx = __half22float2(*(__half2*)&b.x);
        float2 by = __half22float2(*(__half2*)&b.y);
        r.x += ax.x + bx.x + o.x;
        r.y += ax.y + bx.y + o.y;
        r.z += ay.x + by.x + o.z;
        r.w += ay.y + by.y + o.w;
        res[idx] = r;
    }
}

// ---------------------------------------------------------------------------
extern "C" void kernel_launch(void* const* d_in, const int* in_sizes, int n_in,
                              void* d_out, int out_size) {
    const float*  entity_emb = (const float*)d_in[0];
    const void*   edge_index = d_in[1];
    const void*   edge_type  = d_in[2];
    const float*  weight     = (const float*)d_in[3];

    const int n_ent = in_sizes[0] / C_DIM;     // 50000
    const int E     = in_sizes[2];             // 1600000
    const int n_rel = in_sizes[3] / C_DIM;     // 10

    const int TB = 256;
    const int n_vec = n_ent * C_VEC;
    const int scan_blocks = (n_ent + SCAN_TPB - 1) / SCAN_TPB;

    // CSR build + fp16 convert (once per launch; reused across the 3 hops)
    init_convert_kernel<<<(n_vec + TB - 1) / TB, TB>>>(
        (const unsigned*)edge_index, (const float4*)entity_emb, n_ent, n_vec);
    build_a_kernel<<<(E + TB - 1) / TB, TB>>>(edge_index, edge_type, E);
    scan1_kernel<<<scan_blocks, SCAN_TPB>>>(n_ent);
    scan3_kernel<<<scan_blocks, SCAN_TPB>>>(scan_blocks, n_ent);
    build_b_kernel<<<(E + TB - 1) / TB, TB>>>(E);

    // 3 fused hops, one warp per entity (8 warps/block); hop 2 also writes res
    const int hop_blocks = (n_ent * 32 + TB - 1) / TB;
    hop_kernel<<<hop_blocks, TB>>>((const float4*)weight,
                                   (const float4*)entity_emb,
                                   (float4*)d_out, n_ent, n_rel, 0);
    hop_kernel<<<hop_blocks, TB>>>((const float4*)weight,
                                   (const float4*)entity_emb,
                                   (float4*)d_out, n_ent, n_rel, 1);
    hop_kernel<<<hop_blocks, TB>>>((const float4*)weight,
                                   (const float4*)entity_emb,
                                   (float4*)d_out, n_ent, n_rel, 2);
}

// round 17
// speedup vs baseline: 1.6149x; 1.0338x over previous
#include <cuda_runtime.h>
#include <cuda_fp16.h>
#include <cstdint>

#define MAX_ENT   50000
#define MAX_E     1600000
#define MAX_REL   10       // N_REL - 1
#define C_DIM     128
#define C_VEC     (C_DIM / 4)    // 32 float4 per fp32 row
#define C_H2V     (C_DIM / 4)    // 32 uint2 (4 halves) per fp16 row
#define SCAN_TPB  1024

// ---------------- device scratch (static globals: no allocation allowed) ----
// g_cnt invariant: zero at kernel_launch entry.  .bss-zero on module load;
// scan3_kernel re-zeroes it after its final read, so every launch (correctness
// run, capture, every replay) sees identical state and does identical work.
__device__ int            g_head[MAX_E];
__device__ unsigned short g_rank[MAX_E];     // within-head slot from histogram
__device__ unsigned       g_val[MAX_E];      // packed tail | (rel<<20)
__device__ unsigned       g_csr[MAX_E];      // CSR values: packed tail|rel
__device__ int            g_cnt[MAX_ENT];
__device__ int            g_row_start[MAX_ENT + 1];
__device__ int            g_part[64];        // per-block partial sums for scan
__device__ uint2          g_embH[MAX_ENT * C_H2V];  // fp16 input embeddings
__device__ uint2          g_embA[MAX_ENT * C_H2V];  // fp16 hop-1 output
__device__ uint2          g_embB[MAX_ENT * C_H2V];  // fp16 hop-2 output

// ---------------------------------------------------------------------------
// 0) fused: fp32->fp16 embedding convert + edge decode + degree histogram.
//    Width detection per block (shared): int64 ids < 2^31 have all odd 32-bit
//    words zero; effectively impossible for the int32 interpretation of
//    random ids in [0,50000).  The checked lines are L1-resident broadcasts.
__global__ void fused_init_kernel(const void* __restrict__ edge_index,
                                  const void* __restrict__ edge_type,
                                  const float4* __restrict__ emb,
                                  int E, int n_vec) {
    __shared__ int s_is64;
    if (threadIdx.x == 0) {
        const unsigned* words = (const unsigned*)edge_index;
        int is64 = 1;
        #pragma unroll 1
        for (int k = 1; k < 64; k += 2) {
            if (words[k] != 0u) { is64 = 0; break; }
        }
        s_is64 = is64;
    }
    __syncthreads();

    int i = blockIdx.x * blockDim.x + threadIdx.x;

    if (i < n_vec) {
        float4 f = emb[i];
        __half2 a = __floats2half2_rn(f.x, f.y);
        __half2 b = __floats2half2_rn(f.z, f.w);
        uint2 q;
        q.x = *(unsigned*)&a;
        q.y = *(unsigned*)&b;
        g_embH[i] = q;
    }

    if (i < E) {
        int head, tail, rel;
        if (s_is64) {
            const long long* ei = (const long long*)edge_index;
            const long long* et = (const long long*)edge_type;
            head = (int)ei[i];
            tail = (int)ei[E + i];
            rel  = (int)et[i] - 1;
        } else {
            const int* ei = (const int*)edge_index;
            const int* et = (const int*)edge_type;
            head = ei[i];
            tail = ei[E + i];
            rel  = et[i] - 1;
        }
        g_head[i] = head;
        g_val[i]  = (unsigned)tail | ((unsigned)rel << 20);
        int r = atomicAdd(&g_cnt[head], 1);   // g_cnt zero at entry (invariant)
        g_rank[i] = (unsigned short)r;        // degrees ~Poisson(32) << 65536
    }
}

// 1) per-block reduce of g_cnt -> g_part[block]
__global__ void scan1_kernel(int n_ent) {
    __shared__ int s[SCAN_TPB];
    int i = blockIdx.x * SCAN_TPB + threadIdx.x;
    s[threadIdx.x] = (i < n_ent) ? g_cnt[i] : 0;
    __syncthreads();
    for (int off = SCAN_TPB / 2; off > 0; off >>= 1) {
        if (threadIdx.x < off) s[threadIdx.x] += s[threadIdx.x + off];
        __syncthreads();
    }
    if (threadIdx.x == 0) g_part[blockIdx.x] = s[0];
}

// 2) per-block exclusive scan of g_cnt with inline block-offset reduce.
//    Block offset = sum of g_part[b] for b < blockIdx.x (a REDUCE per block).
//    1024-element scan via per-warp shfl scans + one warp-sum scan (3 barriers).
//    Also zeroes g_cnt after the final read (restores the launch invariant).
__global__ void scan3_kernel(int nblocks, int n_ent) {
    __shared__ int s_off;
    __shared__ int wsum[32];

    int tid  = threadIdx.x;
    int warp = tid >> 5;
    int lane = tid & 31;

    // warp 0: reduce partials with index < blockIdx.x (and the grand total)
    if (warp == 0) {
        int a = (lane < blockIdx.x) ? g_part[lane] : 0;
        int b = (lane + 32 < blockIdx.x) ? g_part[lane + 32] : 0;
        int ssum = a + b;
        #pragma unroll
        for (int off = 16; off > 0; off >>= 1)
            ssum += __shfl_xor_sync(0xFFFFFFFFu, ssum, off);
        if (lane == 0) {
            s_off = ssum;
            if (blockIdx.x == gridDim.x - 1)
                g_row_start[n_ent] = ssum + g_part[blockIdx.x];
        }
    }

    int i = blockIdx.x * SCAN_TPB + tid;
    int x = (i < n_ent) ? g_cnt[i] : 0;

    // per-warp inclusive shfl scan
    int v = x;
    #pragma unroll
    for (int off = 1; off < 32; off <<= 1) {
        int t = __shfl_up_sync(0xFFFFFFFFu, v, off);
        if (lane >= off) v += t;
    }
    if (lane == 31) wsum[warp] = v;
    __syncthreads();

    // warp 0: exclusive scan of the 32 warp sums
    if (warp == 0) {
        int w = wsum[lane];
        int ww = w;
        #pragma unroll
        for (int off = 1; off < 32; off <<= 1) {
            int t = __shfl_up_sync(0xFFFFFFFFu, ww, off);
            if (lane >= off) ww += t;
        }
        wsum[lane] = ww - w;                  // exclusive warp offset
    }
    __syncthreads();

    if (i < n_ent) {
        g_row_start[i] = s_off + wsum[warp] + v - x;   // exclusive prefix
        g_cnt[i] = 0;                                   // restore invariant
    }
}

// 3) fill CSR values -- atomic-free: pos = row_start[head] + rank
__global__ void build_b_kernel(int E) {
    int j = blockIdx.x * blockDim.x + threadIdx.x;
    if (j >= E) return;
    int pos = g_row_start[g_head[j]] + (int)g_rank[j];
    g_csr[pos] = g_val[j];
}

// 4) fused hop — R12/R15-proven body: flat 16-wide unroll (16 outstanding
//    uint2 gathers per lane), HFMA2 parity-split accumulators, fp32 combine.
//    hop 0: src embH -> dst embA.   hop 1: embA -> embB.
//    hop 2: embB -> res = emb32 + h1 + h2 + h3  (fused finish).
__global__ __launch_bounds__(256)
void hop_kernel(const float4* __restrict__ weight,
                const float4* __restrict__ emb32,
                float4* __restrict__ res,
                int n_ent, int n_rel, int hop) {
    __shared__ uint2 swh[MAX_REL * C_VEC];   // 2.5 KB: fp16 relation rows
    for (int i = threadIdx.x; i < n_rel * C_VEC; i += blockDim.x) {
        float4 w = weight[i];
        __half2 a = __floats2half2_rn(w.x, w.y);
        __half2 b = __floats2half2_rn(w.z, w.w);
        uint2 q;
        q.x = *(unsigned*)&a;
        q.y = *(unsigned*)&b;
        swh[i] = q;
    }
    __syncthreads();

    const uint2* src = (hop == 0) ? (const uint2*)g_embH
                     : (hop == 1) ? (const uint2*)g_embA
                                  : (const uint2*)g_embB;

    int warp = (blockIdx.x * blockDim.x + threadIdx.x) >> 5;
    int lane = threadIdx.x & 31;
    if (warp >= n_ent) return;

    const int start = g_row_start[warp];
    const int end   = g_row_start[warp + 1];

    const __half2 hz = __float2half2_rn(0.f);
    __half2 aA01 = hz, aA23 = hz;   // even-parity accumulators
    __half2 aB01 = hz, aB23 = hz;   // odd-parity accumulators

    int k = start;
    // 16-wide unroll: 16 independent 64-bit gathers in flight per lane
    for (; k + 15 < end; k += 16) {
        unsigned v[16];
        uint2 p[16];
        #pragma unroll
        for (int u = 0; u < 16; u++) v[u] = g_csr[k + u];
        #pragma unroll
        for (int u = 0; u < 16; u++)
            p[u] = src[(v[u] & 0xFFFFFu) * C_H2V + lane];
        #pragma unroll
        for (int u = 0; u < 16; u++) {
            uint2 w = swh[(v[u] >> 20) * C_VEC + lane];
            __half2 x01 = *(__half2*)&p[u].x;
            __half2 x23 = *(__half2*)&p[u].y;
            __half2 w01 = *(__half2*)&w.x;
            __half2 w23 = *(__half2*)&w.y;
            if (u & 1) {
                aB01 = __hfma2(x01, w01, aB01);
                aB23 = __hfma2(x23, w23, aB23);
            } else {
                aA01 = __hfma2(x01, w01, aA01);
                aA23 = __hfma2(x23, w23, aA23);
            }
        }
    }
    // 8-wide cleanup
    for (; k + 7 < end; k += 8) {
        unsigned v[8];
        uint2 p[8];
        #pragma unroll
        for (int u = 0; u < 8; u++) v[u] = g_csr[k + u];
        #pragma unroll
        for (int u = 0; u < 8; u++)
            p[u] = src[(v[u] & 0xFFFFFu) * C_H2V + lane];
        #pragma unroll
        for (int u = 0; u < 8; u++) {
            uint2 w = swh[(v[u] >> 20) * C_VEC + lane];
            __half2 x01 = *(__half2*)&p[u].x;
            __half2 x23 = *(__half2*)&p[u].y;
            __half2 w01 = *(__half2*)&w.x;
            __half2 w23 = *(__half2*)&w.y;
            if (u & 1) {
                aB01 = __hfma2(x01, w01, aB01);
                aB23 = __hfma2(x23, w23, aB23);
            } else {
                aA01 = __hfma2(x01, w01, aA01);
                aA23 = __hfma2(x23, w23, aA23);
            }
        }
    }
    for (; k < end; k++) {
        unsigned v = g_csr[k];
        uint2 p = src[(v & 0xFFFFFu) * C_H2V + lane];
        uint2 w = swh[(v >> 20) * C_VEC + lane];
        __half2 x01 = *(__half2*)&p.x;
        __half2 x23 = *(__half2*)&p.y;
        __half2 w01 = *(__half2*)&w.x;
        __half2 w23 = *(__half2*)&w.y;
        if (k & 1) {
            aB01 = __hfma2(x01, w01, aB01);
            aB23 = __hfma2(x23, w23, aB23);
        } else {
            aA01 = __hfma2(x01, w01, aA01);
            aA23 = __hfma2(x23, w23, aA23);
        }
    }

    // fp32 combine of the two half2 partial sums
    float2 fA01 = __half22float2(aA01), fB01 = __half22float2(aB01);
    float2 fA23 = __half22float2(aA23), fB23 = __half22float2(aB23);
    float4 acc = make_float4(fA01.x + fB01.x, fA01.y + fB01.y,
                             fA23.x + fB23.x, fA23.y + fB23.y);

    // scatter_mean
    float inv = 1.0f / fmaxf((float)(end - start), 1.0f);
    acc.x *= inv; acc.y *= inv; acc.z *= inv; acc.w *= inv;

    // L2 norm across 128 channels
    float ss = acc.x * acc.x + acc.y * acc.y + acc.z * acc.z + acc.w * acc.w;
    #pragma unroll
    for (int off = 16; off > 0; off >>= 1)
        ss += __shfl_xor_sync(0xFFFFFFFFu, ss, off);
    float scale = 1.0f / fmaxf(sqrtf(ss), 1e-12f);

    float4 o = make_float4(acc.x * scale, acc.y * scale,
                           acc.z * scale, acc.w * scale);

    int idx = warp * C_H2V + lane;

    if (hop < 2) {
        uint2* dst = (hop == 0) ? (uint2*)g_embA : (uint2*)g_embB;
        __half2 ha = __floats2half2_rn(o.x, o.y);
        __half2 hb = __floats2half2_rn(o.z, o.w);
        uint2 q;
        q.x = *(unsigned*)&ha;
        q.y = *(unsigned*)&hb;
        dst[idx] = q;
    } else {
        // fused finish: res = entity_emb + h1 + h2 + h3
        float4 r = emb32[idx];
        uint2 a = g_embA[idx];
        uint2 b = g_embB[idx];
        float2 ax = __half22float2(*(__half2*)&a.x);
        float2 ay = __half22float2(*(__half2*)&a.y);
        float2 bx = __half22float2(*(__half2*)&b.x);
        float2 by = __half22float2(*(__half2*)&b.y);
        r.x += ax.x + bx.x + o.x;
        r.y += ax.y + bx.y + o.y;
        r.z += ay.x + by.x + o.z;
        r.w += ay.y + by.y + o.w;
        res[idx] = r;
    }
}

// ---------------------------------------------------------------------------
extern "C" void kernel_launch(void* const* d_in, const int* in_sizes, int n_in,
                              void* d_out, int out_size) {
    const float*  entity_emb = (const float*)d_in[0];
    const void*   edge_index = d_in[1];
    const void*   edge_type  = d_in[2];
    const float*  weight     = (const float*)d_in[3];

    const int n_ent = in_sizes[0] / C_DIM;     // 50000
    const int E     = in_sizes[2];             // 1600000
    const int n_rel = in_sizes[3] / C_DIM;     // 10

    const int TB = 256;
    const int n_vec = n_ent * C_VEC;
    const int scan_blocks = (n_ent + SCAN_TPB - 1) / SCAN_TPB;
    const int big = (E > n_vec) ? E : n_vec;

    // CSR build + fp16 convert (once per launch; reused across the 3 hops)
    fused_init_kernel<<<(big + TB - 1) / TB, TB>>>(
        edge_index, edge_type, (const float4*)entity_emb, E, n_vec);
    scan1_kernel<<<scan_blocks, SCAN_TPB>>>(n_ent);
    scan3_kernel<<<scan_blocks, SCAN_TPB>>>(scan_blocks, n_ent);
    build_b_kernel<<<(E + TB - 1) / TB, TB>>>(E);

    // 3 fused hops, one warp per entity (8 warps/block); hop 2 also writes res
    const int hop_blocks = (n_ent * 32 + TB - 1) / TB;
    hop_kernel<<<hop_blocks, TB>>>((const float4*)weight,
                                   (const float4*)entity_emb,
                                   (float4*)d_out, n_ent, n_rel, 0);
    hop_kernel<<<hop_blocks, TB>>>((const float4*)weight,
                                   (const float4*)entity_emb,
                                   (float4*)d_out, n_ent, n_rel, 1);
    hop_kernel<<<hop_blocks, TB>>>((const float4*)weight,
                                   (const float4*)entity_emb,
                                   (float4*)d_out, n_ent, n_rel, 2);
}